// round 1
// baseline (speedup 1.0000x reference)
#include <cuda_runtime.h>
#include <math.h>
#include <float.h>
#include <stdint.h>

#define BB 16
#define DD 512
#define TT 2048
#define NQ 9
#define CS 1024
#define CD 8
#define TTILE 64
#define NTHREADS 512

// ---------------- precomputed (normalized) parameter scratch ----------------
__device__ float g_win[NQ * CD * DD];   // weight-normed in_proj  (q, c, d)
__device__ float g_wout[NQ * DD * CD];  // weight-normed out_proj (q, d, c)
__device__ float g_cbn[NQ * CS * CD];   // l2-normalized codebook
__device__ float g_csq[NQ * CS];        // sum(c_norm^2) per code

__global__ void rvq_precompute(const float* __restrict__ iv, const float* __restrict__ ig,
                               const float* __restrict__ ov, const float* __restrict__ og,
                               const float* __restrict__ cb) {
    int q = blockIdx.x;
    int tid = threadIdx.x;           // 256 threads
    int wid = tid >> 5, lane = tid & 31;

    // in_proj: 8 rows of 512, one warp per row
    if (wid < CD) {
        int c = wid;
        const float* v = iv + ((size_t)q * CD + c) * DD;
        float ss = 0.f;
        for (int d = lane; d < DD; d += 32) { float x = v[d]; ss = fmaf(x, x, ss); }
        #pragma unroll
        for (int o = 16; o > 0; o >>= 1) ss += __shfl_xor_sync(0xffffffffu, ss, o);
        float nrm = __fsqrt_rn(ss);
        float g = ig[q * CD + c];
        for (int d = lane; d < DD; d += 32)
            g_win[((size_t)q * CD + c) * DD + d] = __fdiv_rn(g * v[d], nrm);
    }
    // out_proj: 512 rows of 8
    for (int r = tid; r < DD; r += 256) {
        const float* v = ov + ((size_t)q * DD + r) * CD;
        float ss = 0.f;
        #pragma unroll
        for (int c = 0; c < CD; c++) { float x = v[c]; ss = fmaf(x, x, ss); }
        float nrm = __fsqrt_rn(ss);
        float g = og[q * DD + r];
        #pragma unroll
        for (int c = 0; c < CD; c++)
            g_wout[((size_t)q * DD + r) * CD + c] = __fdiv_rn(g * v[c], nrm);
    }
    // codebook: 1024 rows of 8, l2norm with eps, plus csq
    for (int s = tid; s < CS; s += 256) {
        const float* v = cb + ((size_t)q * CS + s) * CD;
        float ss = 0.f;
        #pragma unroll
        for (int c = 0; c < CD; c++) { float x = v[c]; ss = fmaf(x, x, ss); }
        float den = fmaxf(__fsqrt_rn(ss), 1e-12f);
        float cs2 = 0.f;
        #pragma unroll
        for (int c = 0; c < CD; c++) {
            float cn = __fdiv_rn(v[c], den);
            g_cbn[((size_t)q * CS + s) * CD + c] = cn;
            cs2 = fmaf(cn, cn, cs2);
        }
        g_csq[q * CS + s] = cs2;
    }
}

// ---------------- main fused RVQ kernel ----------------
struct SMem {
    float4 cbn4[CS * 2];        // 32 KB  normalized codebook (2 float4 per code)
    float  res[DD][TTILE];      // 128 KB residual tile
    float  win[CD][DD];         // 16 KB
    float  wout[DD][CD];        // 16 KB
    float  csq[CS];             // 4 KB
    float  ob[DD];              // 2 KB
    float  zi[CD][TTILE];
    float  enc[CD][TTILE];
    float  zq[CD][TTILE];
    float  redb[8][TTILE];
    float  encsq[TTILE];
    float  ib[CD];
    int    redi[8][TTILE];
    int    idx[TTILE];
};

__device__ __forceinline__ float dist8(float4 ca, float4 cb2,
                                       float e0, float e1, float e2, float e3,
                                       float e4, float e5, float e6, float e7,
                                       float eq, float cs) {
    float dot = e0 * ca.x;
    dot = fmaf(e1, ca.y, dot); dot = fmaf(e2, ca.z, dot); dot = fmaf(e3, ca.w, dot);
    dot = fmaf(e4, cb2.x, dot); dot = fmaf(e5, cb2.y, dot);
    dot = fmaf(e6, cb2.z, dot); dot = fmaf(e7, cb2.w, dot);
    // matches reference ((enc_sq - 2*dot) + csq): *2 is exact, fma rounds once
    return fmaf(-2.0f, dot, eq) + cs;
}

__global__ void __launch_bounds__(NTHREADS, 1)
rvq_kernel(const float* __restrict__ z,
           const float* __restrict__ ib_g,
           const float* __restrict__ ob_g,
           const float* __restrict__ cbraw,
           float* __restrict__ out) {
    extern __shared__ unsigned char smraw[];
    SMem& sm = *reinterpret_cast<SMem*>(smraw);

    const int tid = threadIdx.x;
    const int b = blockIdx.y;
    const int t0 = blockIdx.x * TTILE;

    // output layout: codes | z_O | z_i_s | z_q_s | z_o_s
    float* out_codes = out;
    float* out_zO  = out + (size_t)BB * NQ * TT;                                   // 294912
    float* out_zis = out_zO + (size_t)BB * DD * TT;                                 // +16.7M
    float* out_zqs = out_zis + (size_t)BB * NQ * CD * TT;
    float* out_zos = out_zqs + (size_t)BB * NQ * CD * TT;

    // ---- load residual tile (vectorized) ----
    const float* zb = z + (size_t)b * DD * TT + t0;
    {
        float4* res4 = reinterpret_cast<float4*>(&sm.res[0][0]);
        for (int f = tid; f < DD * (TTILE / 4); f += NTHREADS) {
            int d = f >> 4, j = f & 15;
            res4[f] = reinterpret_cast<const float4*>(zb + (size_t)d * TT)[j];
        }
    }

    const int t  = tid & (TTILE - 1);   // 0..63
    const int hi = tid >> 6;            // 0..7  (c / chunk / d-group depending on phase)

    for (int q = 0; q < NQ; q++) {
        __syncthreads();   // res ready, previous-q table use done
        // ---- load per-quantizer tables ----
        {
            const float4* s1 = reinterpret_cast<const float4*>(g_win + (size_t)q * CD * DD);
            float4* d1 = reinterpret_cast<float4*>(&sm.win[0][0]);
            for (int i = tid; i < CD * DD / 4; i += NTHREADS) d1[i] = s1[i];
            const float4* s2 = reinterpret_cast<const float4*>(g_wout + (size_t)q * DD * CD);
            float4* d2 = reinterpret_cast<float4*>(&sm.wout[0][0]);
            for (int i = tid; i < DD * CD / 4; i += NTHREADS) d2[i] = s2[i];
            const float4* s3 = reinterpret_cast<const float4*>(g_cbn + (size_t)q * CS * CD);
            for (int i = tid; i < CS * 2; i += NTHREADS) sm.cbn4[i] = s3[i];
            const float4* s4 = reinterpret_cast<const float4*>(g_csq + (size_t)q * CS);
            float4* d4 = reinterpret_cast<float4*>(&sm.csq[0]);
            for (int i = tid; i < CS / 4; i += NTHREADS) d4[i] = s4[i];
            const float4* s5 = reinterpret_cast<const float4*>(ob_g + (size_t)q * DD);
            float4* d5 = reinterpret_cast<float4*>(&sm.ob[0]);
            for (int i = tid; i < DD / 4; i += NTHREADS) d5[i] = s5[i];
            if (tid < CD) sm.ib[tid] = ib_g[q * CD + tid];
        }
        __syncthreads();

        // ---- z_i = w_in @ residual + ib  (thread = (c,t)) ----
        {
            const int c = hi;
            const float* wr = sm.win[c];
            float a0 = 0.f, a1 = 0.f, a2 = 0.f, a3 = 0.f;
            #pragma unroll 4
            for (int d = 0; d < DD; d += 4) {
                a0 = fmaf(wr[d + 0], sm.res[d + 0][t], a0);
                a1 = fmaf(wr[d + 1], sm.res[d + 1][t], a1);
                a2 = fmaf(wr[d + 2], sm.res[d + 2][t], a2);
                a3 = fmaf(wr[d + 3], sm.res[d + 3][t], a3);
            }
            float ziv = ((a0 + a1) + (a2 + a3)) + sm.ib[c];
            sm.zi[c][t] = ziv;
            out_zis[(((size_t)b * NQ + q) * CD + c) * TT + t0 + t] = ziv;
        }
        __syncthreads();

        // ---- l2-normalize enc per column ----
        if (tid < TTILE) {
            float ss = 0.f;
            #pragma unroll
            for (int c = 0; c < CD; c++) { float x = sm.zi[c][tid]; ss = fmaf(x, x, ss); }
            float den = fmaxf(__fsqrt_rn(ss), 1e-12f);
            float es = 0.f;
            #pragma unroll
            for (int c = 0; c < CD; c++) {
                float e = __fdiv_rn(sm.zi[c][tid], den);
                sm.enc[c][tid] = e;
                es = fmaf(e, e, es);
            }
            sm.encsq[tid] = es;
        }
        __syncthreads();

        // ---- nearest-neighbor over 1024 codes (thread = (chunk=hi, t)) ----
        {
            const float e0 = sm.enc[0][t], e1 = sm.enc[1][t], e2 = sm.enc[2][t], e3 = sm.enc[3][t];
            const float e4 = sm.enc[4][t], e5 = sm.enc[5][t], e6 = sm.enc[6][t], e7 = sm.enc[7][t];
            const float eq = sm.encsq[t];
            const int s0 = hi * (CS / 8);
            float b0 = FLT_MAX, b1 = FLT_MAX, b2 = FLT_MAX, b3 = FLT_MAX;
            int   i0 = 0, i1 = 0, i2 = 0, i3 = 0;
            #pragma unroll 2
            for (int s = s0; s < s0 + CS / 8; s += 4) {
                float dA = dist8(sm.cbn4[2 * s + 0], sm.cbn4[2 * s + 1], e0,e1,e2,e3,e4,e5,e6,e7, eq, sm.csq[s + 0]);
                float dB = dist8(sm.cbn4[2 * s + 2], sm.cbn4[2 * s + 3], e0,e1,e2,e3,e4,e5,e6,e7, eq, sm.csq[s + 1]);
                float dC = dist8(sm.cbn4[2 * s + 4], sm.cbn4[2 * s + 5], e0,e1,e2,e3,e4,e5,e6,e7, eq, sm.csq[s + 2]);
                float dDv= dist8(sm.cbn4[2 * s + 6], sm.cbn4[2 * s + 7], e0,e1,e2,e3,e4,e5,e6,e7, eq, sm.csq[s + 3]);
                if (dA < b0) { b0 = dA; i0 = s; }
                if (dB < b1) { b1 = dB; i1 = s + 1; }
                if (dC < b2) { b2 = dC; i2 = s + 2; }
                if (dDv< b3) { b3 = dDv; i3 = s + 3; }
            }
            // merge 4 strided chains, exact first-index tie-break
            if (b1 < b0 || (b1 == b0 && i1 < i0)) { b0 = b1; i0 = i1; }
            if (b2 < b0 || (b2 == b0 && i2 < i0)) { b0 = b2; i0 = i2; }
            if (b3 < b0 || (b3 == b0 && i3 < i0)) { b0 = b3; i0 = i3; }
            sm.redb[hi][t] = b0;
            sm.redi[hi][t] = i0;
        }
        __syncthreads();
        if (tid < TTILE) {
            float bb = sm.redb[0][tid]; int bi = sm.redi[0][tid];
            #pragma unroll
            for (int g = 1; g < 8; g++) {
                float v = sm.redb[g][tid];
                if (v < bb) { bb = v; bi = sm.redi[g][tid]; }   // chunks ascending: tie keeps lower idx
            }
            sm.idx[tid] = bi;
            out_codes[((size_t)b * NQ + q) * TT + t0 + tid] = (float)bi;
        }
        __syncthreads();

        // ---- z_q = z_i + (raw - z_i)  (thread = (c,t)) ----
        {
            const int c = hi;
            int sidx = sm.idx[t];
            float ziv = sm.zi[c][t];
            float raw = __ldg(&cbraw[((size_t)q * CS + sidx) * CD + c]);
            float zqv = ziv + (raw - ziv);
            sm.zq[c][t] = zqv;
            out_zqs[(((size_t)b * NQ + q) * CD + c) * TT + t0 + t] = zqv;
        }
        __syncthreads();

        // ---- z_o = w_out @ z_q + ob ; residual -= z_o  (thread = (dgroup=hi, t)) ----
        {
            const float q0 = sm.zq[0][t], q1 = sm.zq[1][t], q2 = sm.zq[2][t], q3 = sm.zq[3][t];
            const float q4 = sm.zq[4][t], q5 = sm.zq[5][t], q6 = sm.zq[6][t], q7 = sm.zq[7][t];
            const float4* wo4 = reinterpret_cast<const float4*>(&sm.wout[0][0]);
            float* zosb = out_zos + (((size_t)b * NQ + q) * DD) * TT + t0 + t;
            const int dbase = hi * 64;
            #pragma unroll 4
            for (int i = 0; i < 64; i++) {
                int d = dbase + i;
                float4 wa = wo4[2 * d], wb = wo4[2 * d + 1];
                float dot = q0 * wa.x;
                dot = fmaf(q1, wa.y, dot); dot = fmaf(q2, wa.z, dot); dot = fmaf(q3, wa.w, dot);
                dot = fmaf(q4, wb.x, dot); dot = fmaf(q5, wb.y, dot);
                dot = fmaf(q6, wb.z, dot); dot = fmaf(q7, wb.w, dot);
                float zo = dot + sm.ob[d];
                zosb[(size_t)d * TT] = zo;
                sm.res[d][t] = sm.res[d][t] - zo;
            }
        }
    }

    __syncthreads();
    // ---- z_O = z - residual_final ----
    {
        const float* zb2 = zb + t;
        float* zOb = out_zO + (size_t)b * DD * TT + t0 + t;
        const int dbase = hi * 64;
        #pragma unroll 4
        for (int i = 0; i < 64; i++) {
            int d = dbase + i;
            zOb[(size_t)d * TT] = zb2[(size_t)d * TT] - sm.res[d][t];
        }
    }
}

extern "C" void kernel_launch(void* const* d_in, const int* in_sizes, int n_in,
                              void* d_out, int out_size) {
    const float* z    = (const float*)d_in[0];
    const float* in_v = (const float*)d_in[1];
    const float* in_g = (const float*)d_in[2];
    const float* in_b = (const float*)d_in[3];
    const float* out_v= (const float*)d_in[4];
    const float* out_g= (const float*)d_in[5];
    const float* out_b= (const float*)d_in[6];
    const float* cb   = (const float*)d_in[7];
    float* out = (float*)d_out;

    rvq_precompute<<<NQ, 256>>>(in_v, in_g, out_v, out_g, cb);

    static int attr_set = 0;
    (void)attr_set;
    cudaFuncSetAttribute(rvq_kernel, cudaFuncAttributeMaxDynamicSharedMemorySize,
                         (int)sizeof(SMem));
    dim3 grid(TT / TTILE, BB);
    rvq_kernel<<<grid, NTHREADS, sizeof(SMem)>>>(z, in_b, out_b, cb, out);
}